// round 10
// baseline (speedup 1.0000x reference)
#include <cuda_runtime.h>
#include <cuda_bf16.h>
#include <cstdint>

#define N_NODES_MAX 100000
#define E_MAX 1600000
#define OUT_DIM 128
#define IN_DIM 256

// Scratch (device globals per harness rules)
__device__ float g_H[(size_t)N_NODES_MAX * OUT_DIM];   // 51.2 MB
__device__ int   g_cnt[N_NODES_MAX];
__device__ int   g_start[N_NODES_MAX + 1];
__device__ int   g_bsum[512];
__device__ int   g_scol[E_MAX];
__device__ float g_sval[E_MAX];

// W fragments in canonical mma.sync order, lane-indexed for coalesced LDG.64:
// index = ((ch*2 + kstep)*16 + na)*32 + lane ; .x=b0, .y=b1
__device__ uint2 g_WfragHi[8 * 2 * 16 * 32];           // 64 KB
__device__ uint2 g_WfragLo[8 * 2 * 16 * 32];           // 64 KB

// ===========================================================================
// bf16 split helpers
// ===========================================================================
__device__ __forceinline__ void split2(float a, float b,
                                       uint32_t& hi, uint32_t& lo) {
    __nv_bfloat16 ha = __float2bfloat16_rn(a);
    __nv_bfloat16 hb = __float2bfloat16_rn(b);
    __nv_bfloat16 la = __float2bfloat16_rn(a - __bfloat162float(ha));
    __nv_bfloat16 lb = __float2bfloat16_rn(b - __bfloat162float(hb));
    hi = (uint32_t)__bfloat16_as_ushort(ha)
       | ((uint32_t)__bfloat16_as_ushort(hb) << 16);
    lo = (uint32_t)__bfloat16_as_ushort(la)
       | ((uint32_t)__bfloat16_as_ushort(lb) << 16);
}

__device__ __forceinline__ void mma_bf16(float* d, const uint32_t* a,
                                         uint32_t b0, uint32_t b1) {
    asm volatile(
        "mma.sync.aligned.m16n8k16.row.col.f32.bf16.bf16.f32 "
        "{%0,%1,%2,%3}, {%4,%5,%6,%7}, {%8,%9}, {%0,%1,%2,%3};"
        : "+f"(d[0]), "+f"(d[1]), "+f"(d[2]), "+f"(d[3])
        : "r"(a[0]), "r"(a[1]), "r"(a[2]), "r"(a[3]), "r"(b0), "r"(b1));
}

// ===========================================================================
// W fragment precompute: once per launch (~131 KB reads, 128 KB writes).
// B frag (row.col): lane l supplies B[k][n], n = na*8 + l/4,
//   b0: k = ks*16 + (l%4)*2, +1 ; b1: k+8, +9 ; B[k][n] = W[n][k].
// ===========================================================================
__global__ __launch_bounds__(256) void k_wfrag(const float* __restrict__ W)
{
    int idx = blockIdx.x * 256 + threadIdx.x;        // 0 .. 8191
    if (idx >= 8 * 2 * 16 * 32) return;
    int lane = idx & 31;
    int na   = (idx >> 5) & 15;
    int ks   = (idx >> 9) & 1;
    int ch   = idx >> 10;

    int n  = na * 8 + (lane >> 2);
    int k0 = ch * 32 + ks * 16 + (lane & 3) * 2;
    const float* wr = W + (size_t)n * IN_DIM;

    uint32_t h0, l0, h1, l1;
    split2(wr[k0],     wr[k0 + 1], h0, l0);
    split2(wr[k0 + 8], wr[k0 + 9], h1, l1);
    g_WfragHi[idx] = make_uint2(h0, h1);
    g_WfragLo[idx] = make_uint2(l0, l1);
}

// ===========================================================================
// GEMM: H[M,128] = X[M,256] @ W[128,256]^T + b   (3-term bf16 split, ~1e-5)
// Smem-free, syncless: A fragments loaded directly from X (float2 LDG,
// canonical m16n8k16 lane map), converted in registers; B fragments from
// precomputed L2-hot arrays (one coalesced LDG.64 per fragment half).
// Warp w owns rows [blk*128 + w*16, +16); 16 n-atoms; 64 f32 accumulators.
// ===========================================================================
__global__ __launch_bounds__(256) void gcn_gemm_tc(
    const float* __restrict__ X,
    const float* __restrict__ bias,
    int M)
{
    const int w = threadIdx.x >> 5;
    const int l = threadIdx.x & 31;
    const int g = l >> 2;
    const int tc = (l & 3) * 2;

    const int row0 = blockIdx.x * 128 + w * 16 + g;   // rows row0, row0+8
    const bool ok0 = row0 < M;
    const bool ok1 = row0 + 8 < M;
    const float* x0 = X + (size_t)row0 * IN_DIM + tc;
    const float* x1 = x0 + 8 * IN_DIM;

    float d[16][4];
#pragma unroll
    for (int na = 0; na < 16; ++na)
#pragma unroll
        for (int j = 0; j < 4; ++j) d[na][j] = 0.f;

    const float2 z2 = make_float2(0.f, 0.f);

    for (int ch = 0; ch < 8; ++ch) {
#pragma unroll
        for (int ks = 0; ks < 2; ++ks) {
            const int c = ch * 32 + ks * 16;
            // A fragment: a0=[row0,c..c+1], a1=[row0+8], a2=[row0,c+8..9], a3=[row0+8,c+8..9]
            float2 f0 = ok0 ? *(const float2*)(x0 + c)     : z2;
            float2 f1 = ok1 ? *(const float2*)(x1 + c)     : z2;
            float2 f2 = ok0 ? *(const float2*)(x0 + c + 8) : z2;
            float2 f3 = ok1 ? *(const float2*)(x1 + c + 8) : z2;

            uint32_t ah[4], al[4];
            split2(f0.x, f0.y, ah[0], al[0]);
            split2(f1.x, f1.y, ah[1], al[1]);
            split2(f2.x, f2.y, ah[2], al[2]);
            split2(f3.x, f3.y, ah[3], al[3]);

            const uint2* WH = g_WfragHi + ((ch * 2 + ks) * 16) * 32 + l;
            const uint2* WL = g_WfragLo + ((ch * 2 + ks) * 16) * 32 + l;
#pragma unroll
            for (int na = 0; na < 16; ++na) {
                uint2 bh = __ldg(WH + na * 32);
                uint2 bl = __ldg(WL + na * 32);
                mma_bf16(d[na], ah, bh.x, bh.y);   // hi*hi
                mma_bf16(d[na], ah, bl.x, bl.y);   // hi*lo
                mma_bf16(d[na], al, bh.x, bh.y);   // lo*hi
            }
        }
    }

    // epilogue: add bias, store (D frag: d0,d1=[row0, col 2t..], d2,d3=[row0+8])
#pragma unroll
    for (int na = 0; na < 16; ++na) {
        const int col = na * 8 + (l & 3) * 2;
        float2 bv = *(const float2*)(bias + col);
        if (ok0) {
            float2 o = make_float2(d[na][0] + bv.x, d[na][1] + bv.y);
            *(float2*)(g_H + (size_t)row0 * OUT_DIM + col) = o;
        }
        if (ok1) {
            float2 o = make_float2(d[na][2] + bv.x, d[na][3] + bv.y);
            *(float2*)(g_H + (size_t)(row0 + 8) * OUT_DIM + col) = o;
        }
    }
}

// ===========================================================================
// CSR build: counting sort of edges by row
// ===========================================================================
__global__ __launch_bounds__(256) void k_zero(int N) {
    int i = blockIdx.x * 256 + threadIdx.x;
    if (i < N) g_cnt[i] = 0;
}

__global__ __launch_bounds__(256) void k_hist(const int* __restrict__ er, int E) {
    int i = blockIdx.x * 256 + threadIdx.x;
    if (i < E) atomicAdd(&g_cnt[er[i]], 1);
}

__global__ __launch_bounds__(256) void k_scan1(int N) {
    __shared__ int sh[256];
    int i = blockIdx.x * 256 + threadIdx.x;
    int v = (i < N) ? g_cnt[i] : 0;
    sh[threadIdx.x] = v;
    __syncthreads();
#pragma unroll
    for (int off = 1; off < 256; off <<= 1) {
        int t = (threadIdx.x >= off) ? sh[threadIdx.x - off] : 0;
        __syncthreads();
        sh[threadIdx.x] += t;
        __syncthreads();
    }
    if (i < N) g_start[i] = sh[threadIdx.x] - v;
    if (threadIdx.x == 255) g_bsum[blockIdx.x] = sh[255];
}

__global__ __launch_bounds__(512) void k_scan2(int nb) {
    __shared__ int sh[512];
    int t = threadIdx.x;
    int v = (t < nb) ? g_bsum[t] : 0;
    sh[t] = v;
    __syncthreads();
#pragma unroll
    for (int off = 1; off < 512; off <<= 1) {
        int u = (t >= off) ? sh[t - off] : 0;
        __syncthreads();
        sh[t] += u;
        __syncthreads();
    }
    if (t < nb) g_bsum[t] = sh[t] - v;
}

__global__ __launch_bounds__(256) void k_scan3(int N, int E) {
    int i = blockIdx.x * 256 + threadIdx.x;
    if (i < N) {
        int s = g_start[i] + g_bsum[i >> 8];
        g_start[i] = s;
        g_cnt[i] = s;
    }
    if (i == 0) g_start[N] = E;
}

__global__ __launch_bounds__(256) void k_fill(
    const int* __restrict__ er, const int* __restrict__ ec,
    const float* __restrict__ ev, int E)
{
    int i = blockIdx.x * 256 + threadIdx.x;
    if (i < E) {
        int pos = atomicAdd(&g_cnt[er[i]], 1);
        g_scol[pos] = ec[i];
        g_sval[pos] = ev[i];
    }
}

// ===========================================================================
// Gather: one warp per node, register accumulation, no atomics.
// ===========================================================================
__global__ __launch_bounds__(256) void k_gather(float* __restrict__ out, int N)
{
    int warp = (int)((blockIdx.x * (unsigned)blockDim.x + threadIdx.x) >> 5);
    int lane = threadIdx.x & 31;
    if (warp >= N) return;

    int s = g_start[warp];
    int e = g_start[warp + 1];

    float4 acc = make_float4(0.f, 0.f, 0.f, 0.f);
    int j = s;
    for (; j + 4 <= e; j += 4) {
        int   c0 = g_scol[j],     c1 = g_scol[j + 1];
        int   c2 = g_scol[j + 2], c3 = g_scol[j + 3];
        float v0 = g_sval[j],     v1 = g_sval[j + 1];
        float v2 = g_sval[j + 2], v3 = g_sval[j + 3];
        float4 h0 = *(const float4*)(g_H + (size_t)c0 * OUT_DIM + lane * 4);
        float4 h1 = *(const float4*)(g_H + (size_t)c1 * OUT_DIM + lane * 4);
        float4 h2 = *(const float4*)(g_H + (size_t)c2 * OUT_DIM + lane * 4);
        float4 h3 = *(const float4*)(g_H + (size_t)c3 * OUT_DIM + lane * 4);
        acc.x += v0 * h0.x; acc.y += v0 * h0.y; acc.z += v0 * h0.z; acc.w += v0 * h0.w;
        acc.x += v1 * h1.x; acc.y += v1 * h1.y; acc.z += v1 * h1.z; acc.w += v1 * h1.w;
        acc.x += v2 * h2.x; acc.y += v2 * h2.y; acc.z += v2 * h2.z; acc.w += v2 * h2.w;
        acc.x += v3 * h3.x; acc.y += v3 * h3.y; acc.z += v3 * h3.z; acc.w += v3 * h3.w;
    }
    for (; j < e; ++j) {
        int   c = g_scol[j];
        float v = g_sval[j];
        float4 h = *(const float4*)(g_H + (size_t)c * OUT_DIM + lane * 4);
        acc.x += v * h.x; acc.y += v * h.y; acc.z += v * h.z; acc.w += v * h.w;
    }
    *(float4*)(out + (size_t)warp * OUT_DIM + lane * 4) = acc;
}

// ---------------------------------------------------------------------------
// Stream/event for graph fork-join (static init; no device mem involved)
// ---------------------------------------------------------------------------
static cudaStream_t s_aux;
static cudaEvent_t  ev_fork, ev_join;
namespace {
struct InitOnce {
    InitOnce() {
        cudaStreamCreateWithFlags(&s_aux, cudaStreamNonBlocking);
        cudaEventCreateWithFlags(&ev_fork, cudaEventDisableTiming);
        cudaEventCreateWithFlags(&ev_join, cudaEventDisableTiming);
    }
};
InitOnce g_init_once;
}

// ---------------------------------------------------------------------------
// Launch. Input order (metadata): X, edge_row, edge_col, edge_val, W, b.
// main: Wfrag -> GEMM ; aux (concurrent): CSR build ; join -> gather.
// ---------------------------------------------------------------------------
extern "C" void kernel_launch(void* const* d_in, const int* in_sizes, int n_in,
                              void* d_out, int out_size)
{
    const float* X  = (const float*)d_in[0];
    const int*   er = (const int*)d_in[1];
    const int*   ec = (const int*)d_in[2];
    const float* ev = (const float*)d_in[3];
    const float* W  = (const float*)d_in[4];
    const float* b  = (const float*)d_in[5];
    float*      out = (float*)d_out;

    const int M = in_sizes[0] / IN_DIM;     // 100000
    const int E = in_sizes[3];              // 1600000
    const int N = out_size / OUT_DIM;       // 100000

    const int nB = (N + 255) / 256;
    const int eB = (E + 255) / 256;

    // fork: CSR build on aux stream, concurrent with GEMM on main
    cudaEventRecord(ev_fork, 0);
    cudaStreamWaitEvent(s_aux, ev_fork, 0);

    k_zero <<<nB, 256, 0, s_aux>>>(N);
    k_hist <<<eB, 256, 0, s_aux>>>(er, E);
    k_scan1<<<nB, 256, 0, s_aux>>>(N);
    k_scan2<<<1, 512, 0, s_aux>>>(nB);
    k_scan3<<<nB, 256, 0, s_aux>>>(N, E);
    k_fill <<<eB, 256, 0, s_aux>>>(er, ec, ev, E);
    cudaEventRecord(ev_join, s_aux);

    // main stream: W fragments, then GEMM
    k_wfrag<<<32, 256>>>(W);
    gcn_gemm_tc<<<(M + 127) / 128, 256>>>(X, b, M);

    // join, then gather
    cudaStreamWaitEvent(0, ev_join, 0);
    k_gather<<<(N * 32 + 255) / 256, 256>>>(out, N);
}

// round 11
// speedup vs baseline: 1.3538x; 1.3538x over previous
#include <cuda_runtime.h>
#include <cuda_fp16.h>
#include <cstdint>

#define N_NODES_MAX 100000
#define E_MAX 1600000
#define OUT_DIM 128
#define IN_DIM 256

// Scratch (device globals per harness rules)
__device__ float g_H[(size_t)N_NODES_MAX * OUT_DIM];   // 51.2 MB
__device__ int   g_cnt[N_NODES_MAX];
__device__ int   g_start[N_NODES_MAX + 1];
__device__ int   g_bsum[512];
__device__ int   g_scol[E_MAX];
__device__ float g_sval[E_MAX];

// ===========================================================================
// fp16 helpers
// ===========================================================================
__device__ __forceinline__ uint32_t pack_h2(float a, float b) {
    __half2 h = __floats2half2_rn(a, b);
    return *reinterpret_cast<uint32_t*>(&h);
}

// W split (scaled): hi = fp16(w), lo = fp16(w - hi), packed pairwise
__device__ __forceinline__ void wsplit2(float a, float b,
                                        uint32_t& hi, uint32_t& lo) {
    __half ha = __float2half_rn(a);
    __half hb = __float2half_rn(b);
    __half la = __float2half_rn(a - __half2float(ha));
    __half lb = __float2half_rn(b - __half2float(hb));
    hi = (uint32_t)__half_as_ushort(ha) | ((uint32_t)__half_as_ushort(hb) << 16);
    lo = (uint32_t)__half_as_ushort(la) | ((uint32_t)__half_as_ushort(lb) << 16);
}

// warp mma: D[16x8] += A[16x16] * B[16x8], fp16 in, fp32 accum (sm_80 baseline)
__device__ __forceinline__ void mma_f16(float* d, const uint32_t* a,
                                        uint32_t b0, uint32_t b1) {
    asm volatile(
        "mma.sync.aligned.m16n8k16.row.col.f32.f16.f16.f32 "
        "{%0,%1,%2,%3}, {%4,%5,%6,%7}, {%8,%9}, {%0,%1,%2,%3};"
        : "+f"(d[0]), "+f"(d[1]), "+f"(d[2]), "+f"(d[3])
        : "r"(a[0]), "r"(a[1]), "r"(a[2]), "r"(a[3]), "r"(b0), "r"(b1));
}

// ===========================================================================
// GEMM: H[M,128] = X[M,256] @ W[128,256]^T + b
// fp16 2-term: D = Xhi*(Whi + Wlo), W pre-scaled by 256 (descaled in
// epilogue). rel err ~2e-4. BK=32, double-buffered fragment-order smem
// (layout verified conflict-free in R7/R9). 2 MMAs per (n-atom, kstep).
// Per buffer (words): AHI 0 (2176), BHI 2176 (2304), BLO 4480 (2304).
// ===========================================================================
#define BK 32
#define NCHUNK (IN_DIM / BK)     // 8

#define BUF_WORDS 6784
#define SM_AHI 0
#define SM_BHI 2176
#define SM_BLO 4480
#define SM_WORDS (2 * BUF_WORDS)   // 13568 words = 54272 bytes

#define W_SCALE   256.0f
#define W_DESCALE 0.00390625f

__global__ __launch_bounds__(256) void gcn_gemm_tc(
    const float* __restrict__ X,
    const float* __restrict__ W,
    const float* __restrict__ bias,
    int M)
{
    extern __shared__ uint32_t smw[];
    const int tid = threadIdx.x;
    const int w   = tid >> 5;
    const int l   = tid & 31;
    const int rowBase = blockIdx.x * 128;

    float d[16][4];
#pragma unroll
    for (int na = 0; na < 16; ++na)
#pragma unroll
        for (int j = 0; j < 4; ++j) d[na][j] = 0.f;

    const int wr_rl    = l >> 2;
    const int wr_kk4   = (l & 3) * 4;
    const int wr_lane  = wr_rl * 4 + ((wr_kk4 & 7) >> 1);
    const int wr_khalf = wr_kk4 >> 3;

    float4 xq[4], wq[4];

    // ---- stage chunk 0 ----
#pragma unroll
    for (int i = 0; i < 4; ++i) {
        const int rloc  = w * 16 + (i & 1) * 8 + wr_rl;
        const int kstep = i >> 1;
        const int c     = kstep * 16 + wr_kk4;
        const int xrow  = rowBase + rloc;
        xq[i] = (xrow < M) ? *(const float4*)(X + (size_t)xrow * IN_DIM + c)
                           : make_float4(0.f, 0.f, 0.f, 0.f);
        wq[i] = *(const float4*)(W + (size_t)rloc * IN_DIM + c);
    }
    // ---- store chunk 0 into buf 0 ----
#pragma unroll
    for (int i = 0; i < 4; ++i) {
        const int kstep = i >> 1;
        const int rega  = (i & 1) + 2 * wr_khalf;
        // A: fp16 of X, hi only
        const int aidx = (w * 2 + kstep) * 136 + rega * 34 + wr_lane;
        smw[SM_AHI + aidx]     = pack_h2(xq[i].x, xq[i].y);
        smw[SM_AHI + aidx + 1] = pack_h2(xq[i].z, xq[i].w);
        // B: scaled W split hi/lo
        const int rloc   = w * 16 + (i & 1) * 8 + wr_rl;
        const int atom_b = rloc >> 3;
        uint32_t h0, l0, h1, l1;
        wsplit2(wq[i].x * W_SCALE, wq[i].y * W_SCALE, h0, l0);
        wsplit2(wq[i].z * W_SCALE, wq[i].w * W_SCALE, h1, l1);
        const int bidx = (atom_b * 2 + kstep) * 72 + wr_khalf * 36
                       + wr_rl * 4 + ((wr_kk4 & 7) >> 1);
        smw[SM_BHI + bidx]     = h0;
        smw[SM_BHI + bidx + 1] = h1;
        smw[SM_BLO + bidx]     = l0;
        smw[SM_BLO + bidx + 1] = l1;
    }
    __syncthreads();

    for (int ch = 0; ch < NCHUNK; ++ch) {
        const int cur = (ch & 1) * BUF_WORDS;

        // ---- stage chunk ch+1 (LDG latency hidden by MMAs below) ----
        if (ch + 1 < NCHUNK) {
            const int k0n = (ch + 1) * BK;
#pragma unroll
            for (int i = 0; i < 4; ++i) {
                const int rloc  = w * 16 + (i & 1) * 8 + wr_rl;
                const int kstep = i >> 1;
                const int c     = k0n + kstep * 16 + wr_kk4;
                const int xrow  = rowBase + rloc;
                xq[i] = (xrow < M)
                      ? *(const float4*)(X + (size_t)xrow * IN_DIM + c)
                      : make_float4(0.f, 0.f, 0.f, 0.f);
                wq[i] = *(const float4*)(W + (size_t)rloc * IN_DIM + c);
            }
        }

        // ---- compute from current buffer: 2 ksteps x 16 atoms x 2 mma ----
#pragma unroll
        for (int kstep = 0; kstep < 2; ++kstep) {
            uint32_t ah[4];
            const int abase = cur + (w * 2 + kstep) * 136 + l;
#pragma unroll
            for (int j = 0; j < 4; ++j)
                ah[j] = smw[SM_AHI + abase + j * 34];
#pragma unroll
            for (int na = 0; na < 16; ++na) {
                const int bbase = cur + (na * 2 + kstep) * 72 + l;
                uint32_t bh0 = smw[SM_BHI + bbase];
                uint32_t bh1 = smw[SM_BHI + bbase + 36];
                uint32_t bl0 = smw[SM_BLO + bbase];
                uint32_t bl1 = smw[SM_BLO + bbase + 36];
                mma_f16(d[na], ah, bh0, bh1);   // hi * Whi
                mma_f16(d[na], ah, bl0, bl1);   // hi * Wlo
            }
        }

        // ---- convert + store chunk ch+1 into other buffer ----
        if (ch + 1 < NCHUNK) {
            const int nxt = ((ch + 1) & 1) * BUF_WORDS;
#pragma unroll
            for (int i = 0; i < 4; ++i) {
                const int kstep = i >> 1;
                const int rega  = (i & 1) + 2 * wr_khalf;
                const int aidx = nxt + (w * 2 + kstep) * 136 + rega * 34 + wr_lane;
                smw[SM_AHI + aidx]     = pack_h2(xq[i].x, xq[i].y);
                smw[SM_AHI + aidx + 1] = pack_h2(xq[i].z, xq[i].w);

                const int rloc   = w * 16 + (i & 1) * 8 + wr_rl;
                const int atom_b = rloc >> 3;
                uint32_t h0, l0, h1, l1;
                wsplit2(wq[i].x * W_SCALE, wq[i].y * W_SCALE, h0, l0);
                wsplit2(wq[i].z * W_SCALE, wq[i].w * W_SCALE, h1, l1);
                const int bidx = nxt + (atom_b * 2 + kstep) * 72 + wr_khalf * 36
                               + wr_rl * 4 + ((wr_kk4 & 7) >> 1);
                smw[SM_BHI + bidx]     = h0;
                smw[SM_BHI + bidx + 1] = h1;
                smw[SM_BLO + bidx]     = l0;
                smw[SM_BLO + bidx + 1] = l1;
            }
        }
        __syncthreads();
    }

    // ---- epilogue: descale, add bias, store ----
    const int row0 = rowBase + w * 16 + (l >> 2);
    const int row1 = row0 + 8;
#pragma unroll
    for (int na = 0; na < 16; ++na) {
        const int col = na * 8 + (l & 3) * 2;
        float2 bv = *(const float2*)(bias + col);
        if (row0 < M) {
            float2 o = make_float2(fmaf(d[na][0], W_DESCALE, bv.x),
                                   fmaf(d[na][1], W_DESCALE, bv.y));
            *(float2*)(g_H + (size_t)row0 * OUT_DIM + col) = o;
        }
        if (row1 < M) {
            float2 o = make_float2(fmaf(d[na][2], W_DESCALE, bv.x),
                                   fmaf(d[na][3], W_DESCALE, bv.y));
            *(float2*)(g_H + (size_t)row1 * OUT_DIM + col) = o;
        }
    }
}

// ===========================================================================
// CSR build: counting sort of edges by row
// ===========================================================================
__global__ __launch_bounds__(256) void k_zero(int N) {
    int i = blockIdx.x * 256 + threadIdx.x;
    if (i < N) g_cnt[i] = 0;
}

__global__ __launch_bounds__(256) void k_hist(const int* __restrict__ er, int E) {
    int i = blockIdx.x * 256 + threadIdx.x;
    if (i < E) atomicAdd(&g_cnt[er[i]], 1);
}

__global__ __launch_bounds__(256) void k_scan1(int N) {
    __shared__ int sh[256];
    int i = blockIdx.x * 256 + threadIdx.x;
    int v = (i < N) ? g_cnt[i] : 0;
    sh[threadIdx.x] = v;
    __syncthreads();
#pragma unroll
    for (int off = 1; off < 256; off <<= 1) {
        int t = (threadIdx.x >= off) ? sh[threadIdx.x - off] : 0;
        __syncthreads();
        sh[threadIdx.x] += t;
        __syncthreads();
    }
    if (i < N) g_start[i] = sh[threadIdx.x] - v;
    if (threadIdx.x == 255) g_bsum[blockIdx.x] = sh[255];
}

__global__ __launch_bounds__(512) void k_scan2(int nb) {
    __shared__ int sh[512];
    int t = threadIdx.x;
    int v = (t < nb) ? g_bsum[t] : 0;
    sh[t] = v;
    __syncthreads();
#pragma unroll
    for (int off = 1; off < 512; off <<= 1) {
        int u = (t >= off) ? sh[t - off] : 0;
        __syncthreads();
        sh[t] += u;
        __syncthreads();
    }
    if (t < nb) g_bsum[t] = sh[t] - v;
}

__global__ __launch_bounds__(256) void k_scan3(int N, int E) {
    int i = blockIdx.x * 256 + threadIdx.x;
    if (i < N) {
        int s = g_start[i] + g_bsum[i >> 8];
        g_start[i] = s;
        g_cnt[i] = s;
    }
    if (i == 0) g_start[N] = E;
}

__global__ __launch_bounds__(256) void k_fill(
    const int* __restrict__ er, const int* __restrict__ ec,
    const float* __restrict__ ev, int E)
{
    int i = blockIdx.x * 256 + threadIdx.x;
    if (i < E) {
        int pos = atomicAdd(&g_cnt[er[i]], 1);
        g_scol[pos] = ec[i];
        g_sval[pos] = ev[i];
    }
}

// ===========================================================================
// Gather: one warp per node, register accumulation, no atomics.
// ===========================================================================
__global__ __launch_bounds__(256) void k_gather(float* __restrict__ out, int N)
{
    int warp = (int)((blockIdx.x * (unsigned)blockDim.x + threadIdx.x) >> 5);
    int lane = threadIdx.x & 31;
    if (warp >= N) return;

    int s = g_start[warp];
    int e = g_start[warp + 1];

    float4 acc = make_float4(0.f, 0.f, 0.f, 0.f);
    int j = s;
    for (; j + 4 <= e; j += 4) {
        int   c0 = g_scol[j],     c1 = g_scol[j + 1];
        int   c2 = g_scol[j + 2], c3 = g_scol[j + 3];
        float v0 = g_sval[j],     v1 = g_sval[j + 1];
        float v2 = g_sval[j + 2], v3 = g_sval[j + 3];
        float4 h0 = *(const float4*)(g_H + (size_t)c0 * OUT_DIM + lane * 4);
        float4 h1 = *(const float4*)(g_H + (size_t)c1 * OUT_DIM + lane * 4);
        float4 h2 = *(const float4*)(g_H + (size_t)c2 * OUT_DIM + lane * 4);
        float4 h3 = *(const float4*)(g_H + (size_t)c3 * OUT_DIM + lane * 4);
        acc.x += v0 * h0.x; acc.y += v0 * h0.y; acc.z += v0 * h0.z; acc.w += v0 * h0.w;
        acc.x += v1 * h1.x; acc.y += v1 * h1.y; acc.z += v1 * h1.z; acc.w += v1 * h1.w;
        acc.x += v2 * h2.x; acc.y += v2 * h2.y; acc.z += v2 * h2.z; acc.w += v2 * h2.w;
        acc.x += v3 * h3.x; acc.y += v3 * h3.y; acc.z += v3 * h3.z; acc.w += v3 * h3.w;
    }
    for (; j < e; ++j) {
        int   c = g_scol[j];
        float v = g_sval[j];
        float4 h = *(const float4*)(g_H + (size_t)c * OUT_DIM + lane * 4);
        acc.x += v * h.x; acc.y += v * h.y; acc.z += v * h.z; acc.w += v * h.w;
    }
    *(float4*)(out + (size_t)warp * OUT_DIM + lane * 4) = acc;
}

// ---------------------------------------------------------------------------
// Stream/event for graph fork-join (static init; no device mem involved)
// ---------------------------------------------------------------------------
static cudaStream_t s_aux;
static cudaEvent_t  ev_fork, ev_join;
namespace {
struct InitOnce {
    InitOnce() {
        cudaStreamCreateWithFlags(&s_aux, cudaStreamNonBlocking);
        cudaEventCreateWithFlags(&ev_fork, cudaEventDisableTiming);
        cudaEventCreateWithFlags(&ev_join, cudaEventDisableTiming);
    }
};
InitOnce g_init_once;
}

// ---------------------------------------------------------------------------
// Launch. Input order (metadata): X, edge_row, edge_col, edge_val, W, b.
// CSR build runs on a forked stream concurrently with the GEMM; join
// before the gather.
// ---------------------------------------------------------------------------
extern "C" void kernel_launch(void* const* d_in, const int* in_sizes, int n_in,
                              void* d_out, int out_size)
{
    const float* X  = (const float*)d_in[0];
    const int*   er = (const int*)d_in[1];
    const int*   ec = (const int*)d_in[2];
    const float* ev = (const float*)d_in[3];
    const float* W  = (const float*)d_in[4];
    const float* b  = (const float*)d_in[5];
    float*      out = (float*)d_out;

    const int M = in_sizes[0] / IN_DIM;     // 100000
    const int E = in_sizes[3];              // 1600000
    const int N = out_size / OUT_DIM;       // 100000

    cudaFuncSetAttribute(gcn_gemm_tc,
                         cudaFuncAttributeMaxDynamicSharedMemorySize,
                         SM_WORDS * 4);

    const int nB = (N + 255) / 256;
    const int eB = (E + 255) / 256;

    // fork: CSR build on aux stream, concurrent with GEMM on main
    cudaEventRecord(ev_fork, 0);
    cudaStreamWaitEvent(s_aux, ev_fork, 0);

    k_zero <<<nB, 256, 0, s_aux>>>(N);
    k_hist <<<eB, 256, 0, s_aux>>>(er, E);
    k_scan1<<<nB, 256, 0, s_aux>>>(N);
    k_scan2<<<1, 512, 0, s_aux>>>(nB);
    k_scan3<<<nB, 256, 0, s_aux>>>(N, E);
    k_fill <<<eB, 256, 0, s_aux>>>(er, ec, ev, E);
    cudaEventRecord(ev_join, s_aux);

    // GEMM on main stream (overlaps with build)
    gcn_gemm_tc<<<(M + 127) / 128, 256, SM_WORDS * 4>>>(X, W, b, M);

    // join, then gather
    cudaStreamWaitEvent(0, ev_join, 0);
    k_gather<<<(N * 32 + 255) / 256, 256>>>(out, N);
}

// round 12
// speedup vs baseline: 1.4633x; 1.0809x over previous
#include <cuda_runtime.h>
#include <cuda_fp16.h>
#include <cstdint>

#define N_NODES_MAX 100000
#define E_MAX 1600000
#define OUT_DIM 128
#define IN_DIM 256

// Scratch (device globals per harness rules)
__device__ __half g_Hh[(size_t)N_NODES_MAX * OUT_DIM]; // 25.6 MB, fp16 H
__device__ int   g_cnt[N_NODES_MAX];
__device__ int   g_start[N_NODES_MAX + 1];
__device__ int   g_bsum[512];
__device__ int   g_scol[E_MAX];
__device__ float g_sval[E_MAX];

// ===========================================================================
// fp16 helpers
// ===========================================================================
__device__ __forceinline__ uint32_t pack_h2(float a, float b) {
    __half2 h = __floats2half2_rn(a, b);
    return *reinterpret_cast<uint32_t*>(&h);
}

// W split (scaled): hi = fp16(w), lo = fp16(w - hi), packed pairwise
__device__ __forceinline__ void wsplit2(float a, float b,
                                        uint32_t& hi, uint32_t& lo) {
    __half ha = __float2half_rn(a);
    __half hb = __float2half_rn(b);
    __half la = __float2half_rn(a - __half2float(ha));
    __half lb = __float2half_rn(b - __half2float(hb));
    hi = (uint32_t)__half_as_ushort(ha) | ((uint32_t)__half_as_ushort(hb) << 16);
    lo = (uint32_t)__half_as_ushort(la) | ((uint32_t)__half_as_ushort(lb) << 16);
}

// warp mma: D[16x8] += A[16x16] * B[16x8], fp16 in, fp32 accum
__device__ __forceinline__ void mma_f16(float* d, const uint32_t* a,
                                        uint32_t b0, uint32_t b1) {
    asm volatile(
        "mma.sync.aligned.m16n8k16.row.col.f32.f16.f16.f32 "
        "{%0,%1,%2,%3}, {%4,%5,%6,%7}, {%8,%9}, {%0,%1,%2,%3};"
        : "+f"(d[0]), "+f"(d[1]), "+f"(d[2]), "+f"(d[3])
        : "r"(a[0]), "r"(a[1]), "r"(a[2]), "r"(a[3]), "r"(b0), "r"(b1));
}

// ===========================================================================
// GEMM: H[M,128] = X[M,256] @ W[128,256]^T + b   (fp16 2-term, ~2e-4)
// BK=32, double-buffered fragment-order smem. H stored as fp16.
// ===========================================================================
#define BK 32
#define NCHUNK (IN_DIM / BK)     // 8

#define BUF_WORDS 6784
#define SM_AHI 0
#define SM_BHI 2176
#define SM_BLO 4480
#define SM_WORDS (2 * BUF_WORDS)   // 54272 bytes

#define W_SCALE   256.0f
#define W_DESCALE 0.00390625f

__global__ __launch_bounds__(256) void gcn_gemm_tc(
    const float* __restrict__ X,
    const float* __restrict__ W,
    const float* __restrict__ bias,
    int M)
{
    extern __shared__ uint32_t smw[];
    const int tid = threadIdx.x;
    const int w   = tid >> 5;
    const int l   = tid & 31;
    const int rowBase = blockIdx.x * 128;

    float d[16][4];
#pragma unroll
    for (int na = 0; na < 16; ++na)
#pragma unroll
        for (int j = 0; j < 4; ++j) d[na][j] = 0.f;

    const int wr_rl    = l >> 2;
    const int wr_kk4   = (l & 3) * 4;
    const int wr_lane  = wr_rl * 4 + ((wr_kk4 & 7) >> 1);
    const int wr_khalf = wr_kk4 >> 3;

    float4 xq[4], wq[4];

    // ---- stage chunk 0 ----
#pragma unroll
    for (int i = 0; i < 4; ++i) {
        const int rloc  = w * 16 + (i & 1) * 8 + wr_rl;
        const int kstep = i >> 1;
        const int c     = kstep * 16 + wr_kk4;
        const int xrow  = rowBase + rloc;
        xq[i] = (xrow < M) ? *(const float4*)(X + (size_t)xrow * IN_DIM + c)
                           : make_float4(0.f, 0.f, 0.f, 0.f);
        wq[i] = *(const float4*)(W + (size_t)rloc * IN_DIM + c);
    }
    // ---- store chunk 0 into buf 0 ----
#pragma unroll
    for (int i = 0; i < 4; ++i) {
        const int kstep = i >> 1;
        const int rega  = (i & 1) + 2 * wr_khalf;
        const int aidx = (w * 2 + kstep) * 136 + rega * 34 + wr_lane;
        smw[SM_AHI + aidx]     = pack_h2(xq[i].x, xq[i].y);
        smw[SM_AHI + aidx + 1] = pack_h2(xq[i].z, xq[i].w);

        const int rloc   = w * 16 + (i & 1) * 8 + wr_rl;
        const int atom_b = rloc >> 3;
        uint32_t h0, l0, h1, l1;
        wsplit2(wq[i].x * W_SCALE, wq[i].y * W_SCALE, h0, l0);
        wsplit2(wq[i].z * W_SCALE, wq[i].w * W_SCALE, h1, l1);
        const int bidx = (atom_b * 2 + kstep) * 72 + wr_khalf * 36
                       + wr_rl * 4 + ((wr_kk4 & 7) >> 1);
        smw[SM_BHI + bidx]     = h0;
        smw[SM_BHI + bidx + 1] = h1;
        smw[SM_BLO + bidx]     = l0;
        smw[SM_BLO + bidx + 1] = l1;
    }
    __syncthreads();

    for (int ch = 0; ch < NCHUNK; ++ch) {
        const int cur = (ch & 1) * BUF_WORDS;

        // ---- stage chunk ch+1 ----
        if (ch + 1 < NCHUNK) {
            const int k0n = (ch + 1) * BK;
#pragma unroll
            for (int i = 0; i < 4; ++i) {
                const int rloc  = w * 16 + (i & 1) * 8 + wr_rl;
                const int kstep = i >> 1;
                const int c     = k0n + kstep * 16 + wr_kk4;
                const int xrow  = rowBase + rloc;
                xq[i] = (xrow < M)
                      ? *(const float4*)(X + (size_t)xrow * IN_DIM + c)
                      : make_float4(0.f, 0.f, 0.f, 0.f);
                wq[i] = *(const float4*)(W + (size_t)rloc * IN_DIM + c);
            }
        }

        // ---- compute ----
#pragma unroll
        for (int kstep = 0; kstep < 2; ++kstep) {
            uint32_t ah[4];
            const int abase = cur + (w * 2 + kstep) * 136 + l;
#pragma unroll
            for (int j = 0; j < 4; ++j)
                ah[j] = smw[SM_AHI + abase + j * 34];
#pragma unroll
            for (int na = 0; na < 16; ++na) {
                const int bbase = cur + (na * 2 + kstep) * 72 + l;
                uint32_t bh0 = smw[SM_BHI + bbase];
                uint32_t bh1 = smw[SM_BHI + bbase + 36];
                uint32_t bl0 = smw[SM_BLO + bbase];
                uint32_t bl1 = smw[SM_BLO + bbase + 36];
                mma_f16(d[na], ah, bh0, bh1);
                mma_f16(d[na], ah, bl0, bl1);
            }
        }

        // ---- convert + store chunk ch+1 ----
        if (ch + 1 < NCHUNK) {
            const int nxt = ((ch + 1) & 1) * BUF_WORDS;
#pragma unroll
            for (int i = 0; i < 4; ++i) {
                const int kstep = i >> 1;
                const int rega  = (i & 1) + 2 * wr_khalf;
                const int aidx = nxt + (w * 2 + kstep) * 136 + rega * 34 + wr_lane;
                smw[SM_AHI + aidx]     = pack_h2(xq[i].x, xq[i].y);
                smw[SM_AHI + aidx + 1] = pack_h2(xq[i].z, xq[i].w);

                const int rloc   = w * 16 + (i & 1) * 8 + wr_rl;
                const int atom_b = rloc >> 3;
                uint32_t h0, l0, h1, l1;
                wsplit2(wq[i].x * W_SCALE, wq[i].y * W_SCALE, h0, l0);
                wsplit2(wq[i].z * W_SCALE, wq[i].w * W_SCALE, h1, l1);
                const int bidx = nxt + (atom_b * 2 + kstep) * 72 + wr_khalf * 36
                               + wr_rl * 4 + ((wr_kk4 & 7) >> 1);
                smw[SM_BHI + bidx]     = h0;
                smw[SM_BHI + bidx + 1] = h1;
                smw[SM_BLO + bidx]     = l0;
                smw[SM_BLO + bidx + 1] = l1;
            }
        }
        __syncthreads();
    }

    // ---- epilogue: descale, add bias, store H as fp16 ----
    const int row0 = rowBase + w * 16 + (l >> 2);
    const int row1 = row0 + 8;
#pragma unroll
    for (int na = 0; na < 16; ++na) {
        const int col = na * 8 + (l & 3) * 2;
        float2 bv = *(const float2*)(bias + col);
        if (row0 < M) {
            uint32_t p = pack_h2(fmaf(d[na][0], W_DESCALE, bv.x),
                                 fmaf(d[na][1], W_DESCALE, bv.y));
            *(uint32_t*)(g_Hh + (size_t)row0 * OUT_DIM + col) = p;
        }
        if (row1 < M) {
            uint32_t p = pack_h2(fmaf(d[na][2], W_DESCALE, bv.x),
                                 fmaf(d[na][3], W_DESCALE, bv.y));
            *(uint32_t*)(g_Hh + (size_t)row1 * OUT_DIM + col) = p;
        }
    }
}

// ===========================================================================
// CSR build: counting sort of edges by row
// ===========================================================================
__global__ __launch_bounds__(256) void k_zero(int N) {
    int i = blockIdx.x * 256 + threadIdx.x;
    if (i < N) g_cnt[i] = 0;
}

__global__ __launch_bounds__(256) void k_hist(const int* __restrict__ er, int E) {
    int i = blockIdx.x * 256 + threadIdx.x;
    if (i < E) atomicAdd(&g_cnt[er[i]], 1);
}

__global__ __launch_bounds__(256) void k_scan1(int N) {
    __shared__ int sh[256];
    int i = blockIdx.x * 256 + threadIdx.x;
    int v = (i < N) ? g_cnt[i] : 0;
    sh[threadIdx.x] = v;
    __syncthreads();
#pragma unroll
    for (int off = 1; off < 256; off <<= 1) {
        int t = (threadIdx.x >= off) ? sh[threadIdx.x - off] : 0;
        __syncthreads();
        sh[threadIdx.x] += t;
        __syncthreads();
    }
    if (i < N) g_start[i] = sh[threadIdx.x] - v;
    if (threadIdx.x == 255) g_bsum[blockIdx.x] = sh[255];
}

__global__ __launch_bounds__(512) void k_scan2(int nb) {
    __shared__ int sh[512];
    int t = threadIdx.x;
    int v = (t < nb) ? g_bsum[t] : 0;
    sh[t] = v;
    __syncthreads();
#pragma unroll
    for (int off = 1; off < 512; off <<= 1) {
        int u = (t >= off) ? sh[t - off] : 0;
        __syncthreads();
        sh[t] += u;
        __syncthreads();
    }
    if (t < nb) g_bsum[t] = sh[t] - v;
}

__global__ __launch_bounds__(256) void k_scan3(int N, int E) {
    int i = blockIdx.x * 256 + threadIdx.x;
    if (i < N) {
        int s = g_start[i] + g_bsum[i >> 8];
        g_start[i] = s;
        g_cnt[i] = s;
    }
    if (i == 0) g_start[N] = E;
}

__global__ __launch_bounds__(256) void k_fill(
    const int* __restrict__ er, const int* __restrict__ ec,
    const float* __restrict__ ev, int E)
{
    int i = blockIdx.x * 256 + threadIdx.x;
    if (i < E) {
        int pos = atomicAdd(&g_cnt[er[i]], 1);
        g_scol[pos] = ec[i];
        g_sval[pos] = ev[i];
    }
}

// ===========================================================================
// Gather: one warp per node, fp16 H (8B/lane loads), fp32 accumulation.
// ===========================================================================
__device__ __forceinline__ void acc_edge(float4& acc, float v, uint2 raw) {
    __half2 p0 = *reinterpret_cast<__half2*>(&raw.x);
    __half2 p1 = *reinterpret_cast<__half2*>(&raw.y);
    float2 f0 = __half22float2(p0);
    float2 f1 = __half22float2(p1);
    acc.x = fmaf(v, f0.x, acc.x);
    acc.y = fmaf(v, f0.y, acc.y);
    acc.z = fmaf(v, f1.x, acc.z);
    acc.w = fmaf(v, f1.y, acc.w);
}

__global__ __launch_bounds__(256) void k_gather(float* __restrict__ out, int N)
{
    int warp = (int)((blockIdx.x * (unsigned)blockDim.x + threadIdx.x) >> 5);
    int lane = threadIdx.x & 31;
    if (warp >= N) return;

    int s = g_start[warp];
    int e = g_start[warp + 1];

    float4 acc = make_float4(0.f, 0.f, 0.f, 0.f);
    int j = s;
    for (; j + 4 <= e; j += 4) {
        int   c0 = g_scol[j],     c1 = g_scol[j + 1];
        int   c2 = g_scol[j + 2], c3 = g_scol[j + 3];
        float v0 = g_sval[j],     v1 = g_sval[j + 1];
        float v2 = g_sval[j + 2], v3 = g_sval[j + 3];
        uint2 r0 = *(const uint2*)(g_Hh + (size_t)c0 * OUT_DIM + lane * 4);
        uint2 r1 = *(const uint2*)(g_Hh + (size_t)c1 * OUT_DIM + lane * 4);
        uint2 r2 = *(const uint2*)(g_Hh + (size_t)c2 * OUT_DIM + lane * 4);
        uint2 r3 = *(const uint2*)(g_Hh + (size_t)c3 * OUT_DIM + lane * 4);
        acc_edge(acc, v0, r0);
        acc_edge(acc, v1, r1);
        acc_edge(acc, v2, r2);
        acc_edge(acc, v3, r3);
    }
    for (; j < e; ++j) {
        int   c = g_scol[j];
        float v = g_sval[j];
        uint2 r = *(const uint2*)(g_Hh + (size_t)c * OUT_DIM + lane * 4);
        acc_edge(acc, v, r);
    }
    *(float4*)(out + (size_t)warp * OUT_DIM + lane * 4) = acc;
}

// ---------------------------------------------------------------------------
// Stream/event for graph fork-join (static init; no device mem involved)
// ---------------------------------------------------------------------------
static cudaStream_t s_aux;
static cudaEvent_t  ev_fork, ev_join;
namespace {
struct InitOnce {
    InitOnce() {
        cudaStreamCreateWithFlags(&s_aux, cudaStreamNonBlocking);
        cudaEventCreateWithFlags(&ev_fork, cudaEventDisableTiming);
        cudaEventCreateWithFlags(&ev_join, cudaEventDisableTiming);
    }
};
InitOnce g_init_once;
}

// ---------------------------------------------------------------------------
// Launch. Input order (metadata): X, edge_row, edge_col, edge_val, W, b.
// ---------------------------------------------------------------------------
extern "C" void kernel_launch(void* const* d_in, const int* in_sizes, int n_in,
                              void* d_out, int out_size)
{
    const float* X  = (const float*)d_in[0];
    const int*   er = (const int*)d_in[1];
    const int*   ec = (const int*)d_in[2];
    const float* ev = (const float*)d_in[3];
    const float* W  = (const float*)d_in[4];
    const float* b  = (const float*)d_in[5];
    float*      out = (float*)d_out;

    const int M = in_sizes[0] / IN_DIM;     // 100000
    const int E = in_sizes[3];              // 1600000
    const int N = out_size / OUT_DIM;       // 100000

    cudaFuncSetAttribute(gcn_gemm_tc,
                         cudaFuncAttributeMaxDynamicSharedMemorySize,
                         SM_WORDS * 4);

    const int nB = (N + 255) / 256;
    const int eB = (E + 255) / 256;

    // fork: CSR build on aux stream, concurrent with GEMM on main
    cudaEventRecord(ev_fork, 0);
    cudaStreamWaitEvent(s_aux, ev_fork, 0);

    k_zero <<<nB, 256, 0, s_aux>>>(N);
    k_hist <<<eB, 256, 0, s_aux>>>(er, E);
    k_scan1<<<nB, 256, 0, s_aux>>>(N);
    k_scan2<<<1, 512, 0, s_aux>>>(nB);
    k_scan3<<<nB, 256, 0, s_aux>>>(N, E);
    k_fill <<<eB, 256, 0, s_aux>>>(er, ec, ev, E);
    cudaEventRecord(ev_join, s_aux);

    // GEMM on main stream (overlaps with build)
    gcn_gemm_tc<<<(M + 127) / 128, 256, SM_WORDS * 4>>>(X, W, b, M);

    // join, then gather
    cudaStreamWaitEvent(0, ev_join, 0);
    k_gather<<<(N * 32 + 255) / 256, 256>>>(out, N);
}

// round 13
// speedup vs baseline: 1.6152x; 1.1038x over previous
#include <cuda_runtime.h>
#include <cuda_fp16.h>
#include <cstdint>

#define N_NODES_MAX 100000
#define E_MAX 1600000
#define OUT_DIM 128
#define IN_DIM 256

// Scratch (device globals per harness rules)
__device__ __half g_Hh[(size_t)N_NODES_MAX * OUT_DIM]; // 25.6 MB, fp16 H
__device__ int   g_cnt[N_NODES_MAX];
__device__ int   g_start[N_NODES_MAX + 1];
__device__ int   g_bsum[512];
__device__ int   g_scol[E_MAX];
__device__ float g_sval[E_MAX];

// W fragments, canonical m16n8k16 order, lane-major uint2 (.x=b0, .y=b1):
// idx = ((ch*2 + ks)*16 + na)*32 + lane   (mapping verified in R10)
__device__ uint2 g_Wfrag[8 * 2 * 16 * 32];             // 64 KB

// ===========================================================================
// fp16 helpers
// ===========================================================================
__device__ __forceinline__ uint32_t pack_h2(float a, float b) {
    __half2 h = __floats2half2_rn(a, b);
    return *reinterpret_cast<uint32_t*>(&h);
}

// warp mma: D[16x8] += A[16x16] * B[16x8], fp16 in, fp32 accum
__device__ __forceinline__ void mma_f16(float* d, const uint32_t* a,
                                        uint32_t b0, uint32_t b1) {
    asm volatile(
        "mma.sync.aligned.m16n8k16.row.col.f32.f16.f16.f32 "
        "{%0,%1,%2,%3}, {%4,%5,%6,%7}, {%8,%9}, {%0,%1,%2,%3};"
        : "+f"(d[0]), "+f"(d[1]), "+f"(d[2]), "+f"(d[3])
        : "r"(a[0]), "r"(a[1]), "r"(a[2]), "r"(a[3]), "r"(b0), "r"(b1));
}

// ===========================================================================
// W fragment precompute (once per launch, ~3us).
// B frag lane l: n = na*8 + l/4 ; b0: k = ch*32 + ks*16 + (l%4)*2, +1 ;
// b1: k+8, +9 ; B[k][n] = W[n][k].
// ===========================================================================
__global__ __launch_bounds__(256) void k_wfrag(const float* __restrict__ W)
{
    int idx = blockIdx.x * 256 + threadIdx.x;        // 0 .. 8191
    if (idx >= 8 * 2 * 16 * 32) return;
    int lane = idx & 31;
    int na   = (idx >> 5) & 15;
    int ks   = (idx >> 9) & 1;
    int ch   = idx >> 10;

    int n  = na * 8 + (lane >> 2);
    int k0 = ch * 32 + ks * 16 + (lane & 3) * 2;
    const float* wr = W + (size_t)n * IN_DIM;

    g_Wfrag[idx] = make_uint2(pack_h2(wr[k0],     wr[k0 + 1]),
                              pack_h2(wr[k0 + 8], wr[k0 + 9]));
}

// ===========================================================================
// GEMM: H[M,128] = fp16(X) @ fp16(W)^T + b   (single fp16 term, ~3.5e-4)
// B: whole fragment array copied to smem once (64KB, lane-major uint2 ->
// one conflict-free LDS.64 per fragment). A: double-buffered fragment-order
// smem, stride-34 layout (conflict-free, verified R7).
// ===========================================================================
#define BK 32
#define NCHUNK (IN_DIM / BK)     // 8

#define A_BUF_WORDS 2176
#define SM_B_WORDS  16384        // 8192 uint2
#define SM_A0       SM_B_WORDS
#define SM_WORDS    (SM_B_WORDS + 2 * A_BUF_WORDS)   // 20736 words = 82944 B

__global__ __launch_bounds__(256) void gcn_gemm_tc(
    const float* __restrict__ X,
    const float* __restrict__ bias,
    int M)
{
    extern __shared__ uint32_t smw[];
    uint2* smB = reinterpret_cast<uint2*>(smw);
    const int tid = threadIdx.x;
    const int w   = tid >> 5;
    const int l   = tid & 31;
    const int rowBase = blockIdx.x * 128;

    // ---- copy B fragments to smem (coalesced, once) ----
    {
        const uint4* src = reinterpret_cast<const uint4*>(g_Wfrag);
        uint4* dst = reinterpret_cast<uint4*>(smB);
#pragma unroll
        for (int i = 0; i < 16; ++i)
            dst[tid + i * 256] = src[tid + i * 256];
    }

    float d[16][4];
#pragma unroll
    for (int na = 0; na < 16; ++na)
#pragma unroll
        for (int j = 0; j < 4; ++j) d[na][j] = 0.f;

    const int wr_rl    = l >> 2;
    const int wr_kk4   = (l & 3) * 4;
    const int wr_lane  = wr_rl * 4 + ((wr_kk4 & 7) >> 1);
    const int wr_khalf = wr_kk4 >> 3;

    float4 xq[4];

    // ---- stage chunk 0 ----
#pragma unroll
    for (int i = 0; i < 4; ++i) {
        const int rloc  = w * 16 + (i & 1) * 8 + wr_rl;
        const int kstep = i >> 1;
        const int c     = kstep * 16 + wr_kk4;
        const int xrow  = rowBase + rloc;
        xq[i] = (xrow < M) ? *(const float4*)(X + (size_t)xrow * IN_DIM + c)
                           : make_float4(0.f, 0.f, 0.f, 0.f);
    }
#pragma unroll
    for (int i = 0; i < 4; ++i) {
        const int kstep = i >> 1;
        const int rega  = (i & 1) + 2 * wr_khalf;
        const int aidx = SM_A0 + (w * 2 + kstep) * 136 + rega * 34 + wr_lane;
        smw[aidx]     = pack_h2(xq[i].x, xq[i].y);
        smw[aidx + 1] = pack_h2(xq[i].z, xq[i].w);
    }
    __syncthreads();

    for (int ch = 0; ch < NCHUNK; ++ch) {
        const int curA = SM_A0 + (ch & 1) * A_BUF_WORDS;

        // ---- stage chunk ch+1 X (LDG latency hidden by MMAs) ----
        if (ch + 1 < NCHUNK) {
            const int k0n = (ch + 1) * BK;
#pragma unroll
            for (int i = 0; i < 4; ++i) {
                const int rloc  = w * 16 + (i & 1) * 8 + wr_rl;
                const int kstep = i >> 1;
                const int c     = k0n + kstep * 16 + wr_kk4;
                const int xrow  = rowBase + rloc;
                xq[i] = (xrow < M)
                      ? *(const float4*)(X + (size_t)xrow * IN_DIM + c)
                      : make_float4(0.f, 0.f, 0.f, 0.f);
            }
        }

        // ---- compute: 2 ksteps x 16 atoms x 1 mma ----
#pragma unroll
        for (int kstep = 0; kstep < 2; ++kstep) {
            uint32_t ah[4];
            const int abase = curA + (w * 2 + kstep) * 136 + l;
#pragma unroll
            for (int j = 0; j < 4; ++j)
                ah[j] = smw[abase + j * 34];
            const uint2* bp = smB + ((ch * 2 + kstep) * 16) * 32 + l;
#pragma unroll
            for (int na = 0; na < 16; ++na) {
                uint2 b = bp[na * 32];
                mma_f16(d[na], ah, b.x, b.y);
            }
        }

        // ---- convert + store chunk ch+1 A ----
        if (ch + 1 < NCHUNK) {
            const int nxtA = SM_A0 + ((ch + 1) & 1) * A_BUF_WORDS;
#pragma unroll
            for (int i = 0; i < 4; ++i) {
                const int kstep = i >> 1;
                const int rega  = (i & 1) + 2 * wr_khalf;
                const int aidx = nxtA + (w * 2 + kstep) * 136 + rega * 34 + wr_lane;
                smw[aidx]     = pack_h2(xq[i].x, xq[i].y);
                smw[aidx + 1] = pack_h2(xq[i].z, xq[i].w);
            }
        }
        __syncthreads();
    }

    // ---- epilogue: add bias, store H as fp16 ----
    const int row0 = rowBase + w * 16 + (l >> 2);
    const int row1 = row0 + 8;
#pragma unroll
    for (int na = 0; na < 16; ++na) {
        const int col = na * 8 + (l & 3) * 2;
        float2 bv = *(const float2*)(bias + col);
        if (row0 < M) {
            uint32_t p = pack_h2(d[na][0] + bv.x, d[na][1] + bv.y);
            *(uint32_t*)(g_Hh + (size_t)row0 * OUT_DIM + col) = p;
        }
        if (row1 < M) {
            uint32_t p = pack_h2(d[na][2] + bv.x, d[na][3] + bv.y);
            *(uint32_t*)(g_Hh + (size_t)row1 * OUT_DIM + col) = p;
        }
    }
}

// ===========================================================================
// CSR build: counting sort of edges by row
// ===========================================================================
__global__ __launch_bounds__(256) void k_zero(int N) {
    int i = blockIdx.x * 256 + threadIdx.x;
    if (i < N) g_cnt[i] = 0;
}

__global__ __launch_bounds__(256) void k_hist(const int* __restrict__ er, int E) {
    int i = blockIdx.x * 256 + threadIdx.x;
    if (i < E) atomicAdd(&g_cnt[er[i]], 1);
}

__global__ __launch_bounds__(256) void k_scan1(int N) {
    __shared__ int sh[256];
    int i = blockIdx.x * 256 + threadIdx.x;
    int v = (i < N) ? g_cnt[i] : 0;
    sh[threadIdx.x] = v;
    __syncthreads();
#pragma unroll
    for (int off = 1; off < 256; off <<= 1) {
        int t = (threadIdx.x >= off) ? sh[threadIdx.x - off] : 0;
        __syncthreads();
        sh[threadIdx.x] += t;
        __syncthreads();
    }
    if (i < N) g_start[i] = sh[threadIdx.x] - v;
    if (threadIdx.x == 255) g_bsum[blockIdx.x] = sh[255];
}

__global__ __launch_bounds__(512) void k_scan2(int nb) {
    __shared__ int sh[512];
    int t = threadIdx.x;
    int v = (t < nb) ? g_bsum[t] : 0;
    sh[t] = v;
    __syncthreads();
#pragma unroll
    for (int off = 1; off < 512; off <<= 1) {
        int u = (t >= off) ? sh[t - off] : 0;
        __syncthreads();
        sh[t] += u;
        __syncthreads();
    }
    if (t < nb) g_bsum[t] = sh[t] - v;
}

__global__ __launch_bounds__(256) void k_scan3(int N, int E) {
    int i = blockIdx.x * 256 + threadIdx.x;
    if (i < N) {
        int s = g_start[i] + g_bsum[i >> 8];
        g_start[i] = s;
        g_cnt[i] = s;
    }
    if (i == 0) g_start[N] = E;
}

__global__ __launch_bounds__(256) void k_fill(
    const int* __restrict__ er, const int* __restrict__ ec,
    const float* __restrict__ ev, int E)
{
    int i = blockIdx.x * 256 + threadIdx.x;
    if (i < E) {
        int pos = atomicAdd(&g_cnt[er[i]], 1);
        g_scol[pos] = ec[i];
        g_sval[pos] = ev[i];
    }
}

// ===========================================================================
// Gather: one warp per node, fp16 H (8B/lane loads), fp32 accumulation.
// ===========================================================================
__device__ __forceinline__ void acc_edge(float4& acc, float v, uint2 raw) {
    __half2 p0 = *reinterpret_cast<__half2*>(&raw.x);
    __half2 p1 = *reinterpret_cast<__half2*>(&raw.y);
    float2 f0 = __half22float2(p0);
    float2 f1 = __half22float2(p1);
    acc.x = fmaf(v, f0.x, acc.x);
    acc.y = fmaf(v, f0.y, acc.y);
    acc.z = fmaf(v, f1.x, acc.z);
    acc.w = fmaf(v, f1.y, acc.w);
}

__global__ __launch_bounds__(256) void k_gather(float* __restrict__ out, int N)
{
    int warp = (int)((blockIdx.x * (unsigned)blockDim.x + threadIdx.x) >> 5);
    int lane = threadIdx.x & 31;
    if (warp >= N) return;

    int s = g_start[warp];
    int e = g_start[warp + 1];

    float4 acc = make_float4(0.f, 0.f, 0.f, 0.f);
    int j = s;
    for (; j + 4 <= e; j += 4) {
        int   c0 = g_scol[j],     c1 = g_scol[j + 1];
        int   c2 = g_scol[j + 2], c3 = g_scol[j + 3];
        float v0 = g_sval[j],     v1 = g_sval[j + 1];
        float v2 = g_sval[j + 2], v3 = g_sval[j + 3];
        uint2 r0 = *(const uint2*)(g_Hh + (size_t)c0 * OUT_DIM + lane * 4);
        uint2 r1 = *(const uint2*)(g_Hh + (size_t)c1 * OUT_DIM + lane * 4);
        uint2 r2 = *(const uint2*)(g_Hh + (size_t)c2 * OUT_DIM + lane * 4);
        uint2 r3 = *(const uint2*)(g_Hh + (size_t)c3 * OUT_DIM + lane * 4);
        acc_edge(acc, v0, r0);
        acc_edge(acc, v1, r1);
        acc_edge(acc, v2, r2);
        acc_edge(acc, v3, r3);
    }
    for (; j < e; ++j) {
        int   c = g_scol[j];
        float v = g_sval[j];
        uint2 r = *(const uint2*)(g_Hh + (size_t)c * OUT_DIM + lane * 4);
        acc_edge(acc, v, r);
    }
    *(float4*)(out + (size_t)warp * OUT_DIM + lane * 4) = acc;
}

// ---------------------------------------------------------------------------
// Stream/event for graph fork-join (static init; no device mem involved)
// ---------------------------------------------------------------------------
static cudaStream_t s_aux;
static cudaEvent_t  ev_fork, ev_join;
namespace {
struct InitOnce {
    InitOnce() {
        cudaStreamCreateWithFlags(&s_aux, cudaStreamNonBlocking);
        cudaEventCreateWithFlags(&ev_fork, cudaEventDisableTiming);
        cudaEventCreateWithFlags(&ev_join, cudaEventDisableTiming);
    }
};
InitOnce g_init_once;
}

// ---------------------------------------------------------------------------
// Launch. Input order (metadata): X, edge_row, edge_col, edge_val, W, b.
// main: wfrag -> GEMM ; aux (concurrent): CSR build ; join -> gather.
// ---------------------------------------------------------------------------
extern "C" void kernel_launch(void* const* d_in, const int* in_sizes, int n_in,
                              void* d_out, int out_size)
{
    const float* X  = (const float*)d_in[0];
    const int*   er = (const int*)d_in[1];
    const int*   ec = (const int*)d_in[2];
    const float* ev = (const float*)d_in[3];
    const float* W  = (const float*)d_in[4];
    const float* b  = (const float*)d_in[5];
    float*      out = (float*)d_out;

    const int M = in_sizes[0] / IN_DIM;     // 100000
    const int E = in_sizes[3];              // 1600000
    const int N = out_size / OUT_DIM;       // 100000

    cudaFuncSetAttribute(gcn_gemm_tc,
                         cudaFuncAttributeMaxDynamicSharedMemorySize,
                         SM_WORDS * 4);

    const int nB = (N + 255) / 256;
    const int eB = (E + 255) / 256;

    // fork: CSR build on aux stream, concurrent with GEMM on main
    cudaEventRecord(ev_fork, 0);
    cudaStreamWaitEvent(s_aux, ev_fork, 0);

    k_zero <<<nB, 256, 0, s_aux>>>(N);
    k_hist <<<eB, 256, 0, s_aux>>>(er, E);
    k_scan1<<<nB, 256, 0, s_aux>>>(N);
    k_scan2<<<1, 512, 0, s_aux>>>(nB);
    k_scan3<<<nB, 256, 0, s_aux>>>(N, E);
    k_fill <<<eB, 256, 0, s_aux>>>(er, ec, ev, E);
    cudaEventRecord(ev_join, s_aux);

    // main stream: W fragments once, then GEMM
    k_wfrag<<<32, 256>>>(W);
    gcn_gemm_tc<<<(M + 127) / 128, 256, SM_WORDS * 4>>>(X, b, M);

    // join, then gather
    cudaStreamWaitEvent(0, ev_join, 0);
    k_gather<<<(N * 32 + 255) / 256, 256>>>(out, N);
}

// round 14
// speedup vs baseline: 1.6219x; 1.0041x over previous
#include <cuda_runtime.h>
#include <cuda_fp16.h>
#include <cstdint>

#define N_NODES_MAX 100000
#define E_MAX 1600000
#define OUT_DIM 128
#define IN_DIM 256

// Scratch (device globals per harness rules)
__device__ __half g_Hh[(size_t)N_NODES_MAX * OUT_DIM]; // 25.6 MB, fp16 H
__device__ int   g_cnt[N_NODES_MAX];
__device__ int   g_start[N_NODES_MAX + 1];
__device__ int   g_bsum[512];
__device__ int   g_scol[E_MAX];
__device__ float g_sval[E_MAX];

// W fragments, canonical m16n8k16 order, lane-major uint2 (.x=b0, .y=b1):
// idx = ((ch*2 + ks)*16 + na)*32 + lane   (mapping verified in R10)
__device__ uint2 g_Wfrag[8 * 2 * 16 * 32];             // 64 KB

// ===========================================================================
// fp16 helpers
// ===========================================================================
__device__ __forceinline__ uint32_t pack_h2(float a, float b) {
    __half2 h = __floats2half2_rn(a, b);
    return *reinterpret_cast<uint32_t*>(&h);
}

// warp mma: D[16x8] += A[16x16] * B[16x8], fp16 in, fp32 accum
__device__ __forceinline__ void mma_f16(float* d, const uint32_t* a,
                                        uint32_t b0, uint32_t b1) {
    asm volatile(
        "mma.sync.aligned.m16n8k16.row.col.f32.f16.f16.f32 "
        "{%0,%1,%2,%3}, {%4,%5,%6,%7}, {%8,%9}, {%0,%1,%2,%3};"
        : "+f"(d[0]), "+f"(d[1]), "+f"(d[2]), "+f"(d[3])
        : "r"(a[0]), "r"(a[1]), "r"(a[2]), "r"(a[3]), "r"(b0), "r"(b1));
}

// ===========================================================================
// W fragment precompute (once per launch, ~3us).
// B frag lane l: n = na*8 + l/4 ; b0: k = ch*32 + ks*16 + (l%4)*2, +1 ;
// b1: k+8, +9 ; B[k][n] = W[n][k].
// ===========================================================================
__global__ __launch_bounds__(256) void k_wfrag(const float* __restrict__ W)
{
    int idx = blockIdx.x * 256 + threadIdx.x;        // 0 .. 8191
    if (idx >= 8 * 2 * 16 * 32) return;
    int lane = idx & 31;
    int na   = (idx >> 5) & 15;
    int ks   = (idx >> 9) & 1;
    int ch   = idx >> 10;

    int n  = na * 8 + (lane >> 2);
    int k0 = ch * 32 + ks * 16 + (lane & 3) * 2;
    const float* wr = W + (size_t)n * IN_DIM;

    g_Wfrag[idx] = make_uint2(pack_h2(wr[k0],     wr[k0 + 1]),
                              pack_h2(wr[k0 + 8], wr[k0 + 9]));
}

// ===========================================================================
// GEMM: H[M,128] = fp16(X) @ fp16(W)^T + b   (single fp16 term, ~3.5e-4)
// B: whole fragment array copied to smem once (64KB, lane-major uint2 ->
// one conflict-free LDS.64 per fragment). A: double-buffered fragment-order
// smem, stride-34 layout (conflict-free, verified R7).
// ===========================================================================
#define BK 32
#define NCHUNK (IN_DIM / BK)     // 8

#define A_BUF_WORDS 2176
#define SM_B_WORDS  16384        // 8192 uint2
#define SM_A0       SM_B_WORDS
#define SM_WORDS    (SM_B_WORDS + 2 * A_BUF_WORDS)   // 20736 words = 82944 B

__global__ __launch_bounds__(256) void gcn_gemm_tc(
    const float* __restrict__ X,
    const float* __restrict__ bias,
    int M)
{
    extern __shared__ uint32_t smw[];
    uint2* smB = reinterpret_cast<uint2*>(smw);
    const int tid = threadIdx.x;
    const int w   = tid >> 5;
    const int l   = tid & 31;
    const int rowBase = blockIdx.x * 128;

    // ---- copy B fragments to smem (coalesced, once) ----
    {
        const uint4* src = reinterpret_cast<const uint4*>(g_Wfrag);
        uint4* dst = reinterpret_cast<uint4*>(smB);
#pragma unroll
        for (int i = 0; i < 16; ++i)
            dst[tid + i * 256] = src[tid + i * 256];
    }

    float d[16][4];
#pragma unroll
    for (int na = 0; na < 16; ++na)
#pragma unroll
        for (int j = 0; j < 4; ++j) d[na][j] = 0.f;

    const int wr_rl    = l >> 2;
    const int wr_kk4   = (l & 3) * 4;
    const int wr_lane  = wr_rl * 4 + ((wr_kk4 & 7) >> 1);
    const int wr_khalf = wr_kk4 >> 3;

    float4 xq[4];

    // ---- stage chunk 0 ----
#pragma unroll
    for (int i = 0; i < 4; ++i) {
        const int rloc  = w * 16 + (i & 1) * 8 + wr_rl;
        const int kstep = i >> 1;
        const int c     = kstep * 16 + wr_kk4;
        const int xrow  = rowBase + rloc;
        xq[i] = (xrow < M) ? *(const float4*)(X + (size_t)xrow * IN_DIM + c)
                           : make_float4(0.f, 0.f, 0.f, 0.f);
    }
#pragma unroll
    for (int i = 0; i < 4; ++i) {
        const int kstep = i >> 1;
        const int rega  = (i & 1) + 2 * wr_khalf;
        const int aidx = SM_A0 + (w * 2 + kstep) * 136 + rega * 34 + wr_lane;
        smw[aidx]     = pack_h2(xq[i].x, xq[i].y);
        smw[aidx + 1] = pack_h2(xq[i].z, xq[i].w);
    }
    __syncthreads();

    for (int ch = 0; ch < NCHUNK; ++ch) {
        const int curA = SM_A0 + (ch & 1) * A_BUF_WORDS;

        // ---- stage chunk ch+1 X (LDG latency hidden by MMAs) ----
        if (ch + 1 < NCHUNK) {
            const int k0n = (ch + 1) * BK;
#pragma unroll
            for (int i = 0; i < 4; ++i) {
                const int rloc  = w * 16 + (i & 1) * 8 + wr_rl;
                const int kstep = i >> 1;
                const int c     = k0n + kstep * 16 + wr_kk4;
                const int xrow  = rowBase + rloc;
                xq[i] = (xrow < M)
                      ? *(const float4*)(X + (size_t)xrow * IN_DIM + c)
                      : make_float4(0.f, 0.f, 0.f, 0.f);
            }
        }

        // ---- compute: 2 ksteps x 16 atoms x 1 mma ----
#pragma unroll
        for (int kstep = 0; kstep < 2; ++kstep) {
            uint32_t ah[4];
            const int abase = curA + (w * 2 + kstep) * 136 + l;
#pragma unroll
            for (int j = 0; j < 4; ++j)
                ah[j] = smw[abase + j * 34];
            const uint2* bp = smB + ((ch * 2 + kstep) * 16) * 32 + l;
#pragma unroll
            for (int na = 0; na < 16; ++na) {
                uint2 b = bp[na * 32];
                mma_f16(d[na], ah, b.x, b.y);
            }
        }

        // ---- convert + store chunk ch+1 A ----
        if (ch + 1 < NCHUNK) {
            const int nxtA = SM_A0 + ((ch + 1) & 1) * A_BUF_WORDS;
#pragma unroll
            for (int i = 0; i < 4; ++i) {
                const int kstep = i >> 1;
                const int rega  = (i & 1) + 2 * wr_khalf;
                const int aidx = nxtA + (w * 2 + kstep) * 136 + rega * 34 + wr_lane;
                smw[aidx]     = pack_h2(xq[i].x, xq[i].y);
                smw[aidx + 1] = pack_h2(xq[i].z, xq[i].w);
            }
        }
        __syncthreads();
    }

    // ---- epilogue: add bias, store H as fp16 ----
    const int row0 = rowBase + w * 16 + (l >> 2);
    const int row1 = row0 + 8;
#pragma unroll
    for (int na = 0; na < 16; ++na) {
        const int col = na * 8 + (l & 3) * 2;
        float2 bv = *(const float2*)(bias + col);
        if (row0 < M) {
            uint32_t p = pack_h2(d[na][0] + bv.x, d[na][1] + bv.y);
            *(uint32_t*)(g_Hh + (size_t)row0 * OUT_DIM + col) = p;
        }
        if (row1 < M) {
            uint32_t p = pack_h2(d[na][2] + bv.x, d[na][3] + bv.y);
            *(uint32_t*)(g_Hh + (size_t)row1 * OUT_DIM + col) = p;
        }
    }
}

// ===========================================================================
// CSR build: counting sort of edges by row
// ===========================================================================
__global__ __launch_bounds__(256) void k_zero(int N) {
    int i = blockIdx.x * 256 + threadIdx.x;
    if (i < N) g_cnt[i] = 0;
}

__global__ __launch_bounds__(256) void k_hist(const int* __restrict__ er, int E) {
    int i = blockIdx.x * 256 + threadIdx.x;
    if (i < E) atomicAdd(&g_cnt[er[i]], 1);
}

__global__ __launch_bounds__(256) void k_scan1(int N) {
    __shared__ int sh[256];
    int i = blockIdx.x * 256 + threadIdx.x;
    int v = (i < N) ? g_cnt[i] : 0;
    sh[threadIdx.x] = v;
    __syncthreads();
#pragma unroll
    for (int off = 1; off < 256; off <<= 1) {
        int t = (threadIdx.x >= off) ? sh[threadIdx.x - off] : 0;
        __syncthreads();
        sh[threadIdx.x] += t;
        __syncthreads();
    }
    if (i < N) g_start[i] = sh[threadIdx.x] - v;
    if (threadIdx.x == 255) g_bsum[blockIdx.x] = sh[255];
}

__global__ __launch_bounds__(512) void k_scan2(int nb) {
    __shared__ int sh[512];
    int t = threadIdx.x;
    int v = (t < nb) ? g_bsum[t] : 0;
    sh[t] = v;
    __syncthreads();
#pragma unroll
    for (int off = 1; off < 512; off <<= 1) {
        int u = (t >= off) ? sh[t - off] : 0;
        __syncthreads();
        sh[t] += u;
        __syncthreads();
    }
    if (t < nb) g_bsum[t] = sh[t] - v;
}

__global__ __launch_bounds__(256) void k_scan3(int N, int E) {
    int i = blockIdx.x * 256 + threadIdx.x;
    if (i < N) {
        int s = g_start[i] + g_bsum[i >> 8];
        g_start[i] = s;
        g_cnt[i] = s;
    }
    if (i == 0) g_start[N] = E;
}

__global__ __launch_bounds__(256) void k_fill(
    const int* __restrict__ er, const int* __restrict__ ec,
    const float* __restrict__ ev, int E)
{
    int i = blockIdx.x * 256 + threadIdx.x;
    if (i < E) {
        int pos = atomicAdd(&g_cnt[er[i]], 1);
        g_scol[pos] = ec[i];
        g_sval[pos] = ev[i];
    }
}

// ===========================================================================
// Gather: one warp per node, fp16 H (8B/lane loads), fp32 accumulation.
// ===========================================================================
__device__ __forceinline__ void acc_edge(float4& acc, float v, uint2 raw) {
    __half2 p0 = *reinterpret_cast<__half2*>(&raw.x);
    __half2 p1 = *reinterpret_cast<__half2*>(&raw.y);
    float2 f0 = __half22float2(p0);
    float2 f1 = __half22float2(p1);
    acc.x = fmaf(v, f0.x, acc.x);
    acc.y = fmaf(v, f0.y, acc.y);
    acc.z = fmaf(v, f1.x, acc.z);
    acc.w = fmaf(v, f1.y, acc.w);
}

__global__ __launch_bounds__(256) void k_gather(float* __restrict__ out, int N)
{
    int warp = (int)((blockIdx.x * (unsigned)blockDim.x + threadIdx.x) >> 5);
    int lane = threadIdx.x & 31;
    if (warp >= N) return;

    int s = g_start[warp];
    int e = g_start[warp + 1];

    float4 acc = make_float4(0.f, 0.f, 0.f, 0.f);
    int j = s;
    for (; j + 4 <= e; j += 4) {
        int   c0 = g_scol[j],     c1 = g_scol[j + 1];
        int   c2 = g_scol[j + 2], c3 = g_scol[j + 3];
        float v0 = g_sval[j],     v1 = g_sval[j + 1];
        float v2 = g_sval[j + 2], v3 = g_sval[j + 3];
        uint2 r0 = *(const uint2*)(g_Hh + (size_t)c0 * OUT_DIM + lane * 4);
        uint2 r1 = *(const uint2*)(g_Hh + (size_t)c1 * OUT_DIM + lane * 4);
        uint2 r2 = *(const uint2*)(g_Hh + (size_t)c2 * OUT_DIM + lane * 4);
        uint2 r3 = *(const uint2*)(g_Hh + (size_t)c3 * OUT_DIM + lane * 4);
        acc_edge(acc, v0, r0);
        acc_edge(acc, v1, r1);
        acc_edge(acc, v2, r2);
        acc_edge(acc, v3, r3);
    }
    for (; j < e; ++j) {
        int   c = g_scol[j];
        float v = g_sval[j];
        uint2 r = *(const uint2*)(g_Hh + (size_t)c * OUT_DIM + lane * 4);
        acc_edge(acc, v, r);
    }
    *(float4*)(out + (size_t)warp * OUT_DIM + lane * 4) = acc;
}

// ---------------------------------------------------------------------------
// Stream/event for graph fork-join (static init; no device mem involved)
// ---------------------------------------------------------------------------
static cudaStream_t s_aux;
static cudaEvent_t  ev_fork, ev_join;
namespace {
struct InitOnce {
    InitOnce() {
        cudaStreamCreateWithFlags(&s_aux, cudaStreamNonBlocking);
        cudaEventCreateWithFlags(&ev_fork, cudaEventDisableTiming);
        cudaEventCreateWithFlags(&ev_join, cudaEventDisableTiming);
    }
};
InitOnce g_init_once;
}

// ---------------------------------------------------------------------------
// Launch. Input order (metadata): X, edge_row, edge_col, edge_val, W, b.
// main: wfrag -> GEMM ; aux (concurrent): CSR build ; join -> gather.
// ---------------------------------------------------------------------------
extern "C" void kernel_launch(void* const* d_in, const int* in_sizes, int n_in,
                              void* d_out, int out_size)
{
    const float* X  = (const float*)d_in[0];
    const int*   er = (const int*)d_in[1];
    const int*   ec = (const int*)d_in[2];
    const float* ev = (const float*)d_in[3];
    const float* W  = (const float*)d_in[4];
    const float* b  = (const float*)d_in[5];
    float*      out = (float*)d_out;

    const int M = in_sizes[0] / IN_DIM;     // 100000
    const int E = in_sizes[3];              // 1600000
    const int N = out_size / OUT_DIM;       // 100000

    cudaFuncSetAttribute(gcn_gemm_tc,
                         cudaFuncAttributeMaxDynamicSharedMemorySize,
                         SM_WORDS * 4);

    const int nB = (N + 255) / 256;
    const int eB = (E + 255) / 256;

    // fork: CSR build on aux stream, concurrent with GEMM on main
    cudaEventRecord(ev_fork, 0);
    cudaStreamWaitEvent(s_aux, ev_fork, 0);

    k_zero <<<nB, 256, 0, s_aux>>>(N);
    k_hist <<<eB, 256, 0, s_aux>>>(er, E);
    k_scan1<<<nB, 256, 0, s_aux>>>(N);
    k_scan2<<<1, 512, 0, s_aux>>>(nB);
    k_scan3<<<nB, 256, 0, s_aux>>>(N, E);
    k_fill <<<eB, 256, 0, s_aux>>>(er, ec, ev, E);
    cudaEventRecord(ev_join, s_aux);

    // main stream: W fragments once, then GEMM
    k_wfrag<<<32, 256>>>(W);
    gcn_gemm_tc<<<(M + 127) / 128, 256, SM_WORDS * 4>>>(X, b, M);

    // join, then gather
    cudaStreamWaitEvent(0, ev_join, 0);
    k_gather<<<(N * 32 + 255) / 256, 256>>>(out, N);
}